// round 8
// baseline (speedup 1.0000x reference)
#include <cuda_runtime.h>

// v8: software-pipelined four-step 1024-pt inverse FFT (ref == normalized IDFT).
//   Each warp processes R_PER_WARP consecutive rows. Row r+1 streams into a
//   smem staging buffer via cp.async while row r is computed from the other
//   buffer; the current row's staging buffer is reused as transpose scratch
//   after its registers are loaded. DRAM traffic becomes continuous (async
//   engine) instead of synchronized LDG bursts.
// Per-row math = v7's packed f32x2 FFT-32 / twiddle / XOR-transpose / FFT-32.

#define NFFT 1024
#define WARPS_PER_CTA 4
#define NT (32 * WARPS_PER_CTA)
#define R_PER_WARP 4
#define STAGE_BYTES 8192                      // one row: 4KB re + 4KB im
#define SMEM_BYTES (WARPS_PER_CTA * 2 * STAGE_BYTES)   // 64KB / CTA

typedef unsigned long long u64;

__device__ __forceinline__ u64 pk2(float r, float i) {
    u64 o; asm("mov.b64 %0, {%1, %2};" : "=l"(o) : "f"(r), "f"(i)); return o;
}
__device__ __forceinline__ void unpk2(u64 a, float& r, float& i) {
    asm("mov.b64 {%0, %1}, %2;" : "=f"(r), "=f"(i) : "l"(a));
}
__device__ __forceinline__ u64 add2(u64 a, u64 b) {
    u64 o; asm("add.rn.f32x2 %0, %1, %2;" : "=l"(o) : "l"(a), "l"(b)); return o;
}
__device__ __forceinline__ u64 fma2(u64 a, u64 b, u64 c) {
    u64 o; asm("fma.rn.f32x2 %0, %1, %2, %3;" : "=l"(o) : "l"(a), "l"(b), "l"(c));
    return o;
}

__device__ __forceinline__ int brev5(int x) {
    return ((x & 1) << 4) | ((x & 2) << 2) | (x & 4) | ((x & 8) >> 2) | ((x & 16) >> 4);
}

__device__ __forceinline__ void cpasync16(unsigned smem_addr, const void* gptr) {
    asm volatile("cp.async.cg.shared.global [%0], [%1], 16;"
                 :: "r"(smem_addr), "l"(gptr));
}

// Butterfly, twiddle == 1.
__device__ __forceinline__ void bflyT(u64& A, u64& B, u64 NEG1) {
    const u64 s = add2(A, B);
    B = fma2(B, NEG1, A);
    A = s;
}
// Butterfly, twiddle == +i.
__device__ __forceinline__ void bflyI(u64& A, u64& B, u64 NEG1) {
    const u64 s = add2(A, B);
    const u64 d = fma2(B, NEG1, A);
    float dr, di; unpk2(d, dr, di);
    A = s;
    B = pk2(-di, dr);
}
// Butterfly, general compile-time twiddle (FFMA-imm cmul).
__device__ __forceinline__ void bflyG(u64& A, u64& B, u64 NEG1, float C, float S) {
    const u64 s = add2(A, B);
    const u64 d = fma2(B, NEG1, A);
    float dr, di; unpk2(d, dr, di);
    A = s;
    B = pk2(dr * C - di * S, dr * S + di * C);
}

// In-place radix-2 DIF FFT-32, inverse sign, packed. Output bit-reversed.
__device__ __forceinline__ void fft32_dif_pk(u64* z, u64 NEG1) {
    const float TC[16] = {
        1.0f,           0.98078528040f,  0.92387953251f,  0.83146961230f,
        0.70710678119f, 0.55557023302f,  0.38268343236f,  0.19509032202f,
        0.0f,          -0.19509032202f, -0.38268343236f, -0.55557023302f,
       -0.70710678119f,-0.83146961230f, -0.92387953251f, -0.98078528040f };
    const float TS[16] = {
        0.0f,           0.19509032202f,  0.38268343236f,  0.55557023302f,
        0.70710678119f, 0.83146961230f,  0.92387953251f,  0.98078528040f,
        1.0f,           0.98078528040f,  0.92387953251f,  0.83146961230f,
        0.70710678119f, 0.55557023302f,  0.38268343236f,  0.19509032202f };

    #pragma unroll
    for (int s = 0; s < 5; s++) {
        const int L = 32 >> s;
        const int half = L >> 1;
        #pragma unroll
        for (int s0 = 0; s0 < 32; s0 += L) {
            #pragma unroll
            for (int j = 0; j < half; j++) {
                const int i0 = s0 + j;
                const int i1 = i0 + half;
                const int tw = j << s;
                if (tw == 0)       bflyT(z[i0], z[i1], NEG1);
                else if (tw == 8)  bflyI(z[i0], z[i1], NEG1);
                else               bflyG(z[i0], z[i1], NEG1, TC[tw], TS[tw]);
            }
        }
    }
}

__device__ __forceinline__ float2 cmulf(float2 a, float2 b) {
    return make_float2(a.x * b.x - a.y * b.y, a.x * b.y + a.y * b.x);
}

__global__ void __launch_bounds__(NT)
ifft1024_v8(const float* __restrict__ re,
            const float* __restrict__ im,
            float* __restrict__ out,
            int batch)
{
    extern __shared__ char dsm[];

    const int lane = threadIdx.x & 31;
    const int w    = threadIdx.x >> 5;

    char* stage = dsm + w * (2 * STAGE_BYTES);
    const unsigned stage_sa = (unsigned)__cvta_generic_to_shared(stage);

    const size_t gwarp = (size_t)blockIdx.x * WARPS_PER_CTA + w;
    const size_t row0  = gwarp * R_PER_WARP;

    // Mid-twiddle bases (lane-only; computed once for all rows).
    float2 w1;
    __sincosf(6.135923151542565e-3f * (float)lane, &w1.y, &w1.x);  // W1024^lane
    const float2 wb2 = cmulf(w1, w1);
    const float2 wb4 = cmulf(wb2, wb2);
    const float2 w8  = cmulf(wb4, wb4);
    const float2 w16 = cmulf(w8, w8);
    const float2 w24 = cmulf(w16, w8);
    const u64 NEG1 = pk2(-1.0f, -1.0f);

    // Prologue: prefetch row0 into buf 0.
    {
        const char* rr = (const char*)(re + row0 * NFFT);
        const char* ri = (const char*)(im + row0 * NFFT);
        #pragma unroll
        for (int k = 0; k < 8; k++) {
            const int off = lane * 16 + k * 512;
            cpasync16(stage_sa + off,        rr + off);
            cpasync16(stage_sa + 4096 + off, ri + off);
        }
        asm volatile("cp.async.commit_group;");
    }

    for (int r = 0; r < R_PER_WARP; r++) {
        const unsigned cur_sa = stage_sa + (unsigned)((r & 1) * STAGE_BYTES);
        char* cur = stage + (r & 1) * STAGE_BYTES;

        // Prefetch next row into the other buffer (it was fully consumed as
        // scratch in iteration r-1; per-lane program order + the syncwarp
        // after the transpose reads make this safe warp-wide).
        if (r + 1 < R_PER_WARP) {
            const size_t nrow = row0 + r + 1;
            const char* rr = (const char*)(re + nrow * NFFT);
            const char* ri = (const char*)(im + nrow * NFFT);
            const unsigned nxt_sa = stage_sa + (unsigned)(((r + 1) & 1) * STAGE_BYTES);
            #pragma unroll
            for (int k = 0; k < 8; k++) {
                const int off = lane * 16 + k * 512;
                cpasync16(nxt_sa + off,        rr + off);
                cpasync16(nxt_sa + 4096 + off, ri + off);
            }
        }
        asm volatile("cp.async.commit_group;");       // (possibly empty group)
        asm volatile("cp.async.wait_group 1;");       // row r staged & visible
        __syncwarp();

        // Load row r from staging: x[32a + lane], pack. (LDS.32, CF.)
        const float* sre = (const float*)cur;
        const float* sim = (const float*)(cur + 4096);
        u64 z[32];
        #pragma unroll
        for (int a = 0; a < 32; a++) {
            z[a] = pk2(sre[32 * a + lane], sim[32 * a + lane]);
        }
        __syncwarp();   // all lanes done reading before cur is reused as scratch

        // FFT over a.  z[p] = A[brev5(p), lane].
        fft32_dif_pk(z, NEG1);

        // Apply (1/1024)*W1024^{b*k1} and write the XOR-swizzled transpose
        // into cur (reinterpreted as u64[1024]).
        u64* sb = (u64*)cur;
        {
            float2 ch = make_float2(1.0f / 1024.0f, 0.0f);
            #pragma unroll
            for (int l = 0; l < 8; l++) {
                const float2 tt[4] = { ch, cmulf(ch, w8), cmulf(ch, w16),
                                       cmulf(ch, w24) };
                #pragma unroll
                for (int q = 0; q < 4; q++) {
                    const int k1 = l + 8 * q;
                    const int p  = brev5(k1);
                    float ar, ai; unpk2(z[p], ar, ai);
                    const float2 t = tt[q];
                    sb[(k1 << 5) + (lane ^ k1)] =
                        pk2(ar * t.x - ai * t.y, ar * t.y + ai * t.x);
                }
                ch = cmulf(ch, w1);
            }
        }
        __syncwarp();
        #pragma unroll
        for (int b = 0; b < 32; b++) {
            z[b] = sb[(lane << 5) + (b ^ lane)];
        }
        __syncwarp();   // scratch reads done: next iteration may overwrite

        // FFT over b.  z[p] = X[lane + 32*brev5(p)] (already scaled).
        fft32_dif_pk(z, NEG1);

        // Coalesced stores.
        const size_t row = row0 + r;
        float* __restrict__ outr = out + row * NFFT;
        float* __restrict__ outi = out + (size_t)batch * NFFT + row * NFFT;
        #pragma unroll
        for (int p = 0; p < 32; p++) {
            const int k2 = brev5(p);
            float xr, xi; unpk2(z[p], xr, xi);
            outr[lane + 32 * k2] = xr;
            outi[lane + 32 * k2] = xi;
        }
    }
}

extern "C" void kernel_launch(void* const* d_in, const int* in_sizes, int n_in,
                              void* d_out, int out_size)
{
    // metadata order: re, im, wr_u, wr_l, wi_u, wi_l (matrices unused: the
    // u/l split sums exactly to the IDFT matrix; the reference pipeline is a
    // normalized 1024-point inverse DFT, computed here directly).
    const float* re = (const float*)d_in[0];
    const float* im = (const float*)d_in[1];
    float* out = (float*)d_out;

    const int batch = in_sizes[0] / NFFT;            // 32768
    const int rows_per_cta = WARPS_PER_CTA * R_PER_WARP;   // 16

    static bool attr_set = false;
    if (!attr_set) {
        cudaFuncSetAttribute(ifft1024_v8,
                             cudaFuncAttributeMaxDynamicSharedMemorySize,
                             SMEM_BYTES);
        attr_set = true;
    }
    ifft1024_v8<<<batch / rows_per_cta, NT, SMEM_BYTES>>>(re, im, out, batch);
}